// round 7
// baseline (speedup 1.0000x reference)
#include <cuda_runtime.h>
#include <cuda_bf16.h>
#include <cstdint>

#define B_  32
#define T_  1024
#define S_  1024
#define D_  512
#define K2_ 1024          // 2*D
#define M_  (B_ * T_)     // 32768

// GEMM tiling
#define BM 128
#define BN 256
#define BKc 32            // k per chunk (two m16n8k16 k-steps)
#define NCH (K2_ / BKc)   // 32 chunks
#define NSTAGE 3

// smem layout (bytes, per stage): rows 64B data + 16B pad = 80B stride
// (conflict-free ldmatrix: r*80 mod 128 -> word offsets {0,20,8,28,16,4,24,12})
#define A_ROW   80
#define A_HI_OFF 0
#define A_LO_OFF (128 * A_ROW)            // 10240
#define W_HI_OFF (2 * 128 * A_ROW)        // 20480
#define W_LO_OFF (W_HI_OFF + 256 * A_ROW) // 40960
#define STAGE_SZ (W_LO_OFF + 256 * A_ROW) // 61440
#define SMEM_TOTAL (NSTAGE * STAGE_SZ)    // 184320

// ---------------------------------------------------------------------------
// device scratch (module globals)
// ---------------------------------------------------------------------------
__device__ int d_j[M_];
__device__ __align__(16) __nv_bfloat16 d_Whi[D_ * K2_];
__device__ __align__(16) __nv_bfloat16 d_Wlo[D_ * K2_];
__device__ __align__(16) __nv_bfloat16 d_Ahi[(size_t)M_ * K2_];
__device__ __align__(16) __nv_bfloat16 d_Alo[(size_t)M_ * K2_];

// ---------------------------------------------------------------------------
// PTX helpers
// ---------------------------------------------------------------------------
__device__ __forceinline__ uint32_t smem_u32(const void* p) {
    uint32_t a;
    asm("{ .reg .u64 t; cvta.to.shared.u64 t, %1; cvt.u32.u64 %0, t; }"
        : "=r"(a) : "l"(p));
    return a;
}
__device__ __forceinline__ void cp16(uint32_t dst, const void* src) {
    asm volatile("cp.async.cg.shared.global [%0], [%1], 16;" :: "r"(dst), "l"(src));
}
#define CP_COMMIT() asm volatile("cp.async.commit_group;" ::: "memory")
#define CP_WAIT(n)  asm volatile("cp.async.wait_group %0;" :: "n"(n) : "memory")

__device__ __forceinline__ void ldsm4(uint32_t* r, uint32_t addr) {
    asm volatile("ldmatrix.sync.aligned.m8n8.x4.shared.b16 {%0,%1,%2,%3}, [%4];"
                 : "=r"(r[0]), "=r"(r[1]), "=r"(r[2]), "=r"(r[3]) : "r"(addr));
}
__device__ __forceinline__ void mma16816(float* c, const uint32_t* a,
                                         uint32_t b0, uint32_t b1) {
    asm volatile(
        "mma.sync.aligned.m16n8k16.row.col.f32.bf16.bf16.f32 "
        "{%0,%1,%2,%3}, {%4,%5,%6,%7}, {%8,%9}, {%0,%1,%2,%3};"
        : "+f"(c[0]), "+f"(c[1]), "+f"(c[2]), "+f"(c[3])
        : "r"(a[0]), "r"(a[1]), "r"(a[2]), "r"(a[3]), "r"(b0), "r"(b1));
}
__device__ __forceinline__ void split_bf16(float v, __nv_bfloat16& h, __nv_bfloat16& l) {
    h = __float2bfloat16(v);
    l = __float2bfloat16(v - __bfloat162float(h));
}

// ---------------------------------------------------------------------------
// 1) j indices (token buffer int32 or int64 — detected on device)
// ---------------------------------------------------------------------------
__global__ void compute_j_kernel(const int* __restrict__ w32) {
    __shared__ int s[T_];
    __shared__ int is64_s;
    const int b = blockIdx.x;
    const int t = threadIdx.x;
    if (t == 0) {
        int allzero = 1;
        #pragma unroll
        for (int i = 1; i < 64; i += 2) allzero &= (w32[i] == 0);
        is64_s = allzero;
    }
    __syncthreads();
    const int idx = b * T_ + t;
    const int tok = is64_s ? w32[idx * 2] : w32[idx];
    int flag = (t >= 1 && (tok == 1 || tok == 2)) ? 1 : 0;
    s[t] = flag;
    __syncthreads();
    #pragma unroll
    for (int off = 1; off < T_; off <<= 1) {
        int v = (t >= off) ? s[t - off] : 0;
        __syncthreads();
        s[t] += v;
        __syncthreads();
    }
    int jj;
    if (t == 0) jj = 0;
    else { jj = t - s[t] - 1; if (jj < 0) jj += S_; }
    d_j[idx] = jj;
}

// ---------------------------------------------------------------------------
// 2) attn: write one-hot rows directly (fused zero+scatter, pure streaming)
// ---------------------------------------------------------------------------
__global__ void write_attn_kernel(float* __restrict__ attn) {
    const int m = blockIdx.x;
    const int t = threadIdx.x;          // 256 threads x float4 = 1024 cols
    const int j = d_j[m];
    float4 v = make_float4(0.f, 0.f, 0.f, 0.f);
    if ((j >> 2) == t) ((float*)&v)[j & 3] = 1.0f;
    ((float4*)(attn + (size_t)m * S_))[t] = v;
}

// ---------------------------------------------------------------------------
// 3) prep: W -> bf16 hi/lo; A -> bf16 hi/lo (gathered rows)
// ---------------------------------------------------------------------------
__global__ void prep_w_kernel(const float* __restrict__ W) {
    const int n = blockIdx.x;
    const int col = threadIdx.x * 4;
    float4 v = *(const float4*)(W + (size_t)n * K2_ + col);
    __nv_bfloat16 hx, hy, hz, hw, lx, ly, lz, lw;
    split_bf16(v.x, hx, lx); split_bf16(v.y, hy, ly);
    split_bf16(v.z, hz, lz); split_bf16(v.w, hw, lw);
    union { __nv_bfloat162 h2[2]; uint2 u; } ph, pl;
    ph.h2[0] = __halves2bfloat162(hx, hy); ph.h2[1] = __halves2bfloat162(hz, hw);
    pl.h2[0] = __halves2bfloat162(lx, ly); pl.h2[1] = __halves2bfloat162(lz, lw);
    *(uint2*)(d_Whi + (size_t)n * K2_ + col) = ph.u;
    *(uint2*)(d_Wlo + (size_t)n * K2_ + col) = pl.u;
}

__global__ void prep_a_kernel(const float* __restrict__ outp,     // [M, D]
                              const float* __restrict__ context)  // [B, S, D]
{
    const int m = blockIdx.x;
    const int t = threadIdx.x;        // 256 threads x 4 floats = 1024 cols
    const int col = t * 4;
    const int bb = m >> 10;
    const int jm = d_j[m];
    const float* src = (t < 128)
        ? context + ((size_t)((bb << 10) + jm)) * D_ + col
        : outp + (size_t)m * D_ + (col - D_);
    float4 v = *(const float4*)src;
    __nv_bfloat16 hx, hy, hz, hw, lx, ly, lz, lw;
    split_bf16(v.x, hx, lx); split_bf16(v.y, hy, ly);
    split_bf16(v.z, hz, lz); split_bf16(v.w, hw, lw);
    union { __nv_bfloat162 h2[2]; uint2 u; } ph, pl;
    ph.h2[0] = __halves2bfloat162(hx, hy); ph.h2[1] = __halves2bfloat162(hz, hw);
    pl.h2[0] = __halves2bfloat162(lx, ly); pl.h2[1] = __halves2bfloat162(lz, lw);
    *(uint2*)(d_Ahi + (size_t)m * K2_ + col) = ph.u;
    *(uint2*)(d_Alo + (size_t)m * K2_ + col) = pl.u;
}

// ---------------------------------------------------------------------------
// 4) HMMA GEMM: out[m,n] = tanh(bias[n] + sum_k A[m,k]*W[n,k])
//    3-pass bf16 split, CTA 128x256, 8 warps 64x64, K-chunk 32, 3-stage pipeline.
// ---------------------------------------------------------------------------
__global__ __launch_bounds__(256, 1)
void gemm_mma_kernel(const float* __restrict__ bias, float* __restrict__ out)
{
    extern __shared__ char smem[];
    const uint32_t smb = smem_u32(smem);
    const int tid = threadIdx.x;
    const int wid = tid >> 5;
    const int lane = tid & 31;
    const int wm = wid & 1;           // warp m (2)
    const int wn = wid >> 1;          // warp n (4)
    const int m0 = blockIdx.y * BM;
    const int n0 = blockIdx.x * BN;

    float acc[4][8][4];
    #pragma unroll
    for (int i = 0; i < 4; i++)
        #pragma unroll
        for (int j = 0; j < 8; j++)
            #pragma unroll
            for (int k = 0; k < 4; k++) acc[i][j][k] = 0.f;

    // ---- loader: stage s <- chunk c (64B per row per matrix)
    auto issue = [&](int c, int s) {
        const int k0 = c * BKc;
        const uint32_t st = smb + s * STAGE_SZ;
        // A: 128 rows; tid<128 -> hi, else lo; 4x cp16 per row
        {
            const int half = tid >> 7;
            const int r = tid & 127;
            const __nv_bfloat16* src =
                (half ? d_Alo : d_Ahi) + (size_t)(m0 + r) * K2_ + k0;
            const uint32_t dst = st + (half ? A_LO_OFF : A_HI_OFF) + r * A_ROW;
            cp16(dst,      src);
            cp16(dst + 16, src + 8);
            cp16(dst + 32, src + 16);
            cp16(dst + 48, src + 24);
        }
        // W: 256 rows, hi+lo
        {
            const int r = tid;
            const __nv_bfloat16* sh = d_Whi + (size_t)(n0 + r) * K2_ + k0;
            const __nv_bfloat16* sl = d_Wlo + (size_t)(n0 + r) * K2_ + k0;
            const uint32_t dh = st + W_HI_OFF + r * A_ROW;
            const uint32_t dl = st + W_LO_OFF + r * A_ROW;
            cp16(dh, sh); cp16(dh + 16, sh + 8); cp16(dh + 32, sh + 16); cp16(dh + 48, sh + 24);
            cp16(dl, sl); cp16(dl + 16, sl + 8); cp16(dl + 32, sl + 16); cp16(dl + 48, sl + 24);
        }
    };

    // prologue
    #pragma unroll
    for (int s = 0; s < NSTAGE; s++) { issue(s, s); CP_COMMIT(); }

    // ldmatrix lane addressing (k-step base added per ks)
    const uint32_t aoff = (uint32_t)((wm * 64 + (lane & 15)) * A_ROW + (lane >> 4) * 16);
    const int g = lane >> 3;
    const uint32_t boff = (uint32_t)((wn * 64 + ((g >> 1) << 3) + (lane & 7)) * A_ROW
                                     + (g & 1) * 16);

    int stage = 0;
    for (int c = 0; c < NCH; c++) {
        CP_WAIT(2);
        __syncthreads();

        const uint32_t st = smb + stage * STAGE_SZ;
        #pragma unroll
        for (int ks = 0; ks < 2; ks++) {
            const uint32_t kb = ks * 32;
            uint32_t ah[4][4], al[4][4];
            #pragma unroll
            for (int mt = 0; mt < 4; mt++) {
                ldsm4(ah[mt], st + A_HI_OFF + aoff + kb + mt * 16 * A_ROW);
                ldsm4(al[mt], st + A_LO_OFF + aoff + kb + mt * 16 * A_ROW);
            }
            #pragma unroll
            for (int np = 0; np < 4; np++) {
                uint32_t bh[4], bl[4];
                ldsm4(bh, st + W_HI_OFF + boff + kb + np * 16 * A_ROW);
                ldsm4(bl, st + W_LO_OFF + boff + kb + np * 16 * A_ROW);
                #pragma unroll
                for (int mt = 0; mt < 4; mt++) {          // Ah*Wh
                    mma16816(acc[mt][np * 2],     ah[mt], bh[0], bh[1]);
                    mma16816(acc[mt][np * 2 + 1], ah[mt], bh[2], bh[3]);
                }
                #pragma unroll
                for (int mt = 0; mt < 4; mt++) {          // Ah*Wl
                    mma16816(acc[mt][np * 2],     ah[mt], bl[0], bl[1]);
                    mma16816(acc[mt][np * 2 + 1], ah[mt], bl[2], bl[3]);
                }
                #pragma unroll
                for (int mt = 0; mt < 4; mt++) {          // Al*Wh
                    mma16816(acc[mt][np * 2],     al[mt], bh[0], bh[1]);
                    mma16816(acc[mt][np * 2 + 1], al[mt], bh[2], bh[3]);
                }
            }
        }

        __syncthreads();
        if (c + NSTAGE < NCH) issue(c + NSTAGE, stage);
        CP_COMMIT();
        stage = (stage + 1 == NSTAGE) ? 0 : stage + 1;
    }

    // ---- epilogue: bias + tanh, float2 stores
    const int r4 = lane >> 2;
    const int c2 = (lane & 3) * 2;
    #pragma unroll
    for (int mt = 0; mt < 4; mt++) {
        #pragma unroll
        for (int nt = 0; nt < 8; nt++) {
            const int gm = m0 + wm * 64 + mt * 16 + r4;
            const int gn = n0 + wn * 64 + nt * 8 + c2;
            const float b0 = bias[gn], b1 = bias[gn + 1];
            float2 v0, v1;
            v0.x = tanhf(acc[mt][nt][0] + b0);
            v0.y = tanhf(acc[mt][nt][1] + b1);
            v1.x = tanhf(acc[mt][nt][2] + b0);
            v1.y = tanhf(acc[mt][nt][3] + b1);
            *(float2*)(out + (size_t)gm * D_ + gn) = v0;
            *(float2*)(out + (size_t)(gm + 8) * D_ + gn) = v1;
        }
    }
}

// ---------------------------------------------------------------------------
extern "C" void kernel_launch(void* const* d_in, const int* in_sizes, int n_in,
                              void* d_out, int out_size) {
    const int* input_var = nullptr;
    const float* output  = nullptr;
    const float* context = nullptr;
    const float* W    = nullptr;
    const float* bias = nullptr;

    for (int i = 0; i < n_in; i++) {
        const int sz = in_sizes[i];
        if (sz == B_ * T_) input_var = (const int*)d_in[i];
        else if (sz == B_ * T_ * D_) {
            if (!output) output = (const float*)d_in[i];
            else if (!context) context = (const float*)d_in[i];
        } else if (sz == D_ * K2_) W = (const float*)d_in[i];
        else if (sz == D_) bias = (const float*)d_in[i];
    }

    float* out  = (float*)d_out;                 // [B,T,D]
    float* attn = out + (size_t)M_ * D_;         // [B,T,S]

    static bool attr_set = false;
    if (!attr_set) {
        cudaFuncSetAttribute(gemm_mma_kernel,
                             cudaFuncAttributeMaxDynamicSharedMemorySize, SMEM_TOTAL);
        attr_set = true;
    }

    // gemm placed at call-index 3 so ncu (-s 5 -c 1) captures it
    compute_j_kernel<<<B_, T_>>>(input_var);
    prep_w_kernel<<<D_, 256>>>(W);
    prep_a_kernel<<<M_, 256>>>(output, context);
    dim3 grid(D_ / BN, M_ / BM);  // (2, 256)
    gemm_mma_kernel<<<grid, 256, SMEM_TOTAL>>>(bias, out);
    write_attn_kernel<<<M_, 256>>>(attn);
}

// round 8
// speedup vs baseline: 1.0436x; 1.0436x over previous
#include <cuda_runtime.h>
#include <cuda_bf16.h>
#include <cstdint>

#define B_  32
#define T_  1024
#define S_  1024
#define D_  512
#define K2_ 1024          // 2*D
#define M_  (B_ * T_)     // 32768

// GEMM tiling
#define BM 128
#define BN 256
#define BKc 16            // k per chunk (one m16n8k16 k-step)
#define NCH (K2_ / BKc)   // 64 chunks
#define NSTAGE 5

// smem layout (bytes, per stage): rows padded to 48B for conflict-free ldmatrix
#define A_ROW   48
#define A_HI_OFF 0
#define A_LO_OFF (128 * A_ROW)            // 6144
#define W_HI_OFF (2 * 128 * A_ROW)        // 12288
#define W_LO_OFF (W_HI_OFF + 256 * A_ROW) // 24576
#define STAGE_SZ (W_LO_OFF + 256 * A_ROW) // 36864
#define SMEM_TOTAL (NSTAGE * STAGE_SZ)    // 184320

// ---------------------------------------------------------------------------
// device scratch (module globals)
// ---------------------------------------------------------------------------
__device__ int d_j[M_];
__device__ __align__(16) __nv_bfloat16 d_Whi[D_ * K2_];
__device__ __align__(16) __nv_bfloat16 d_Wlo[D_ * K2_];
__device__ __align__(16) __nv_bfloat16 d_Ahi[(size_t)M_ * K2_];
__device__ __align__(16) __nv_bfloat16 d_Alo[(size_t)M_ * K2_];

// ---------------------------------------------------------------------------
// PTX helpers
// ---------------------------------------------------------------------------
__device__ __forceinline__ uint32_t smem_u32(const void* p) {
    uint32_t a;
    asm("{ .reg .u64 t; cvta.to.shared.u64 t, %1; cvt.u32.u64 %0, t; }"
        : "=r"(a) : "l"(p));
    return a;
}
__device__ __forceinline__ void cp16(uint32_t dst, const void* src) {
    asm volatile("cp.async.cg.shared.global [%0], [%1], 16;" :: "r"(dst), "l"(src));
}
#define CP_COMMIT() asm volatile("cp.async.commit_group;" ::: "memory")
#define CP_WAIT(n)  asm volatile("cp.async.wait_group %0;" :: "n"(n) : "memory")

__device__ __forceinline__ void ldsm4(uint32_t* r, uint32_t addr) {
    asm volatile("ldmatrix.sync.aligned.m8n8.x4.shared.b16 {%0,%1,%2,%3}, [%4];"
                 : "=r"(r[0]), "=r"(r[1]), "=r"(r[2]), "=r"(r[3]) : "r"(addr));
}
__device__ __forceinline__ void mma16816(float* c, const uint32_t* a,
                                         uint32_t b0, uint32_t b1) {
    asm volatile(
        "mma.sync.aligned.m16n8k16.row.col.f32.bf16.bf16.f32 "
        "{%0,%1,%2,%3}, {%4,%5,%6,%7}, {%8,%9}, {%0,%1,%2,%3};"
        : "+f"(c[0]), "+f"(c[1]), "+f"(c[2]), "+f"(c[3])
        : "r"(a[0]), "r"(a[1]), "r"(a[2]), "r"(a[3]), "r"(b0), "r"(b1));
}
__device__ __forceinline__ void split_bf16(float v, __nv_bfloat16& h, __nv_bfloat16& l) {
    h = __float2bfloat16(v);
    l = __float2bfloat16(v - __bfloat162float(h));
}

// ---------------------------------------------------------------------------
// 1) j indices (token buffer int32 or int64 — detected on device)
// ---------------------------------------------------------------------------
__global__ void compute_j_kernel(const int* __restrict__ w32) {
    __shared__ int s[T_];
    __shared__ int is64_s;
    const int b = blockIdx.x;
    const int t = threadIdx.x;
    if (t == 0) {
        int allzero = 1;
        #pragma unroll
        for (int i = 1; i < 64; i += 2) allzero &= (w32[i] == 0);
        is64_s = allzero;
    }
    __syncthreads();
    const int idx = b * T_ + t;
    const int tok = is64_s ? w32[idx * 2] : w32[idx];
    int flag = (t >= 1 && (tok == 1 || tok == 2)) ? 1 : 0;
    s[t] = flag;
    __syncthreads();
    #pragma unroll
    for (int off = 1; off < T_; off <<= 1) {
        int v = (t >= off) ? s[t - off] : 0;
        __syncthreads();
        s[t] += v;
        __syncthreads();
    }
    int jj;
    if (t == 0) jj = 0;
    else { jj = t - s[t] - 1; if (jj < 0) jj += S_; }
    d_j[idx] = jj;
}

// ---------------------------------------------------------------------------
// 2) attn: write one-hot rows directly (fused zero+scatter, pure streaming)
// ---------------------------------------------------------------------------
__global__ void write_attn_kernel(float* __restrict__ attn) {
    const int m = blockIdx.x;
    const int t = threadIdx.x;          // 256 threads x float4 = 1024 cols
    const int j = d_j[m];
    float4 v = make_float4(0.f, 0.f, 0.f, 0.f);
    if ((j >> 2) == t) ((float*)&v)[j & 3] = 1.0f;
    ((float4*)(attn + (size_t)m * S_))[t] = v;
}

// ---------------------------------------------------------------------------
// 3) prep: W -> bf16 hi/lo; A -> bf16 hi/lo (gathered rows)
// ---------------------------------------------------------------------------
__global__ void prep_w_kernel(const float* __restrict__ W) {
    const int n = blockIdx.x;
    const int col = threadIdx.x * 4;
    float4 v = *(const float4*)(W + (size_t)n * K2_ + col);
    __nv_bfloat16 hx, hy, hz, hw, lx, ly, lz, lw;
    split_bf16(v.x, hx, lx); split_bf16(v.y, hy, ly);
    split_bf16(v.z, hz, lz); split_bf16(v.w, hw, lw);
    union { __nv_bfloat162 h2[2]; uint2 u; } ph, pl;
    ph.h2[0] = __halves2bfloat162(hx, hy); ph.h2[1] = __halves2bfloat162(hz, hw);
    pl.h2[0] = __halves2bfloat162(lx, ly); pl.h2[1] = __halves2bfloat162(lz, lw);
    *(uint2*)(d_Whi + (size_t)n * K2_ + col) = ph.u;
    *(uint2*)(d_Wlo + (size_t)n * K2_ + col) = pl.u;
}

__global__ void prep_a_kernel(const float* __restrict__ outp,     // [M, D]
                              const float* __restrict__ context)  // [B, S, D]
{
    const int m = blockIdx.x;
    const int t = threadIdx.x;        // 256 threads x 4 floats = 1024 cols
    const int col = t * 4;
    const int bb = m >> 10;
    const int jm = d_j[m];
    const float* src = (t < 128)
        ? context + ((size_t)((bb << 10) + jm)) * D_ + col
        : outp + (size_t)m * D_ + (col - D_);
    float4 v = *(const float4*)src;
    __nv_bfloat16 hx, hy, hz, hw, lx, ly, lz, lw;
    split_bf16(v.x, hx, lx); split_bf16(v.y, hy, ly);
    split_bf16(v.z, hz, lz); split_bf16(v.w, hw, lw);
    union { __nv_bfloat162 h2[2]; uint2 u; } ph, pl;
    ph.h2[0] = __halves2bfloat162(hx, hy); ph.h2[1] = __halves2bfloat162(hz, hw);
    pl.h2[0] = __halves2bfloat162(lx, ly); pl.h2[1] = __halves2bfloat162(lz, lw);
    *(uint2*)(d_Ahi + (size_t)m * K2_ + col) = ph.u;
    *(uint2*)(d_Alo + (size_t)m * K2_ + col) = pl.u;
}

// ---------------------------------------------------------------------------
// 4) HMMA GEMM: out[m,n] = tanh(bias[n] + sum_k A[m,k]*W[n,k])
//    3-pass bf16 split, CTA 128x256, 8 warps 64x64, K-chunk 16,
//    5-stage cp.async pipeline, ONE __syncthreads per chunk.
// ---------------------------------------------------------------------------
__global__ __launch_bounds__(256, 1)
void gemm_mma_kernel(const float* __restrict__ bias, float* __restrict__ out)
{
    extern __shared__ char smem[];
    const uint32_t smb = smem_u32(smem);
    const int tid = threadIdx.x;
    const int wid = tid >> 5;
    const int lane = tid & 31;
    const int wm = wid & 1;           // warp m (2)
    const int wn = wid >> 1;          // warp n (4)
    const int m0 = blockIdx.y * BM;
    const int n0 = blockIdx.x * BN;

    float acc[4][8][4];
    #pragma unroll
    for (int i = 0; i < 4; i++)
        #pragma unroll
        for (int j = 0; j < 8; j++)
            #pragma unroll
            for (int k = 0; k < 4; k++) acc[i][j][k] = 0.f;

    // ---- loader: stage s <- chunk c
    auto issue = [&](int c, int s) {
        const int k0 = c * BKc;
        const uint32_t st = smb + s * STAGE_SZ;
        {
            const int half = tid >> 7;
            const int r = tid & 127;
            const __nv_bfloat16* src =
                (half ? d_Alo : d_Ahi) + (size_t)(m0 + r) * K2_ + k0;
            const uint32_t dst = st + (half ? A_LO_OFF : A_HI_OFF) + r * A_ROW;
            cp16(dst,      src);
            cp16(dst + 16, src + 8);
        }
        {
            const int r = tid;
            const __nv_bfloat16* sh = d_Whi + (size_t)(n0 + r) * K2_ + k0;
            const __nv_bfloat16* sl = d_Wlo + (size_t)(n0 + r) * K2_ + k0;
            const uint32_t dh = st + W_HI_OFF + r * A_ROW;
            const uint32_t dl = st + W_LO_OFF + r * A_ROW;
            cp16(dh, sh); cp16(dh + 16, sh + 8);
            cp16(dl, sl); cp16(dl + 16, sl + 8);
        }
    };

    // prologue: fill stages 0..3 (keep one stage of write slack)
    #pragma unroll
    for (int s = 0; s < NSTAGE - 1; s++) { issue(s, s); CP_COMMIT(); }

    // ldmatrix lane addressing
    const uint32_t aoff = (uint32_t)((wm * 64 + (lane & 15)) * A_ROW + (lane >> 4) * 16);
    const int g = lane >> 3;
    const uint32_t boff = (uint32_t)((wn * 64 + ((g >> 1) << 3) + (lane & 7)) * A_ROW
                                     + (g & 1) * 16);

    int stage = 0;
    int wstage = NSTAGE - 1;
    for (int c = 0; c < NCH; c++) {
        CP_WAIT(3);
        __syncthreads();
        // fill the stage consumed at iter c-1 (all warps passed the sync above)
        if (c + NSTAGE - 1 < NCH) issue(c + NSTAGE - 1, wstage);
        CP_COMMIT();

        const uint32_t st = smb + stage * STAGE_SZ;
        uint32_t ah[4][4], al[4][4];
        #pragma unroll
        for (int mt = 0; mt < 4; mt++) {
            ldsm4(ah[mt], st + A_HI_OFF + aoff + mt * 16 * A_ROW);
            ldsm4(al[mt], st + A_LO_OFF + aoff + mt * 16 * A_ROW);
        }
        #pragma unroll
        for (int np = 0; np < 4; np++) {
            uint32_t bh[4], bl[4];
            ldsm4(bh, st + W_HI_OFF + boff + np * 16 * A_ROW);
            ldsm4(bl, st + W_LO_OFF + boff + np * 16 * A_ROW);
            #pragma unroll
            for (int mt = 0; mt < 4; mt++) {          // Ah*Wh
                mma16816(acc[mt][np * 2],     ah[mt], bh[0], bh[1]);
                mma16816(acc[mt][np * 2 + 1], ah[mt], bh[2], bh[3]);
            }
            #pragma unroll
            for (int mt = 0; mt < 4; mt++) {          // Ah*Wl
                mma16816(acc[mt][np * 2],     ah[mt], bl[0], bl[1]);
                mma16816(acc[mt][np * 2 + 1], ah[mt], bl[2], bl[3]);
            }
            #pragma unroll
            for (int mt = 0; mt < 4; mt++) {          // Al*Wh
                mma16816(acc[mt][np * 2],     al[mt], bh[0], bh[1]);
                mma16816(acc[mt][np * 2 + 1], al[mt], bh[2], bh[3]);
            }
        }

        stage  = (stage  + 1 == NSTAGE) ? 0 : stage + 1;
        wstage = (wstage + 1 == NSTAGE) ? 0 : wstage + 1;
    }

    // ---- epilogue: bias + tanh, float2 stores
    const int r4 = lane >> 2;
    const int c2 = (lane & 3) * 2;
    #pragma unroll
    for (int mt = 0; mt < 4; mt++) {
        #pragma unroll
        for (int nt = 0; nt < 8; nt++) {
            const int gm = m0 + wm * 64 + mt * 16 + r4;
            const int gn = n0 + wn * 64 + nt * 8 + c2;
            const float b0 = bias[gn], b1 = bias[gn + 1];
            float2 v0, v1;
            v0.x = tanhf(acc[mt][nt][0] + b0);
            v0.y = tanhf(acc[mt][nt][1] + b1);
            v1.x = tanhf(acc[mt][nt][2] + b0);
            v1.y = tanhf(acc[mt][nt][3] + b1);
            *(float2*)(out + (size_t)gm * D_ + gn) = v0;
            *(float2*)(out + (size_t)(gm + 8) * D_ + gn) = v1;
        }
    }
}

// ---------------------------------------------------------------------------
extern "C" void kernel_launch(void* const* d_in, const int* in_sizes, int n_in,
                              void* d_out, int out_size) {
    const int* input_var = nullptr;
    const float* output  = nullptr;
    const float* context = nullptr;
    const float* W    = nullptr;
    const float* bias = nullptr;

    for (int i = 0; i < n_in; i++) {
        const int sz = in_sizes[i];
        if (sz == B_ * T_) input_var = (const int*)d_in[i];
        else if (sz == B_ * T_ * D_) {
            if (!output) output = (const float*)d_in[i];
            else if (!context) context = (const float*)d_in[i];
        } else if (sz == D_ * K2_) W = (const float*)d_in[i];
        else if (sz == D_) bias = (const float*)d_in[i];
    }

    float* out  = (float*)d_out;                 // [B,T,D]
    float* attn = out + (size_t)M_ * D_;         // [B,T,S]

    static bool attr_set = false;
    if (!attr_set) {
        cudaFuncSetAttribute(gemm_mma_kernel,
                             cudaFuncAttributeMaxDynamicSharedMemorySize, SMEM_TOTAL);
        attr_set = true;
    }

    // gemm placed at call-index 3 so ncu (-s 5 -c 1) captures it
    compute_j_kernel<<<B_, T_>>>(input_var);
    prep_w_kernel<<<D_, 256>>>(W);
    prep_a_kernel<<<M_, 256>>>(output, context);
    dim3 grid(D_ / BN, M_ / BM);  // (2, 256)
    gemm_mma_kernel<<<grid, 256, SMEM_TOTAL>>>(bias, out);
    write_attn_kernel<<<M_, 256>>>(attn);
}